// round 2
// baseline (speedup 1.0000x reference)
#include <cuda_runtime.h>
#include <stdint.h>

// Problem constants
#define NB    32
#define CIN   256
#define HH    56
#define WW    56
#define COUT  256
#define NWORD 8          // 256 channels / 32 bits
#define WPAD  (WW + 2)   // zero-padded columns
#define BN_EPS 1e-5f

// Scratch (no allocations allowed): packed sign bits
// x packed: [n][h][w][word]   bit b of word wd = (x[n][32*wd+b][h][w] > 0)
__device__ uint32_t g_xp[(size_t)NB * HH * WW * NWORD];
// w packed: [tap][word][co]   (co contiguous -> coalesced register fill)
__device__ uint32_t g_wp[9 * NWORD * COUT];

// ---------------------------------------------------------------------------
// Pack activations: one block per (n,h); thread t -> (word wd, column w)
// ---------------------------------------------------------------------------
__global__ void pack_x_kernel(const float* __restrict__ x) {
    int b = blockIdx.x;            // n*56 + h
    int n = b / HH, h = b % HH;
    int t = threadIdx.x;
    if (t >= WW * NWORD) return;
    int wd = t / WW;
    int w  = t % WW;
    const float* xb = x + ((size_t)n * CIN + (size_t)wd * 32) * (HH * WW)
                        + (size_t)h * WW + w;
    uint32_t bits = 0;
    #pragma unroll
    for (int c = 0; c < 32; ++c) {
        float v = __ldg(xb + (size_t)c * (HH * WW));
        bits |= (v > 0.0f) ? (1u << c) : 0u;
    }
    g_xp[((size_t)b * WW + w) * NWORD + wd] = bits;
}

// ---------------------------------------------------------------------------
// Pack weights: gid = (tap*8 + wd)*256 + co
// ---------------------------------------------------------------------------
__global__ void pack_w_kernel(const float* __restrict__ wt) {
    int gid = blockIdx.x * blockDim.x + threadIdx.x;
    if (gid >= 9 * NWORD * COUT) return;
    int co  = gid & (COUT - 1);
    int tw  = gid >> 8;            // tap*8 + wd
    int tap = tw >> 3;
    int wd  = tw & 7;
    const float* wb = wt + ((size_t)co * CIN + (size_t)wd * 32) * 9 + tap;
    uint32_t bits = 0;
    #pragma unroll
    for (int c = 0; c < 32; ++c) {
        float v = __ldg(wb + c * 9);
        bits |= (v > 0.0f) ? (1u << c) : 0u;
    }
    g_wp[gid] = bits;
}

// ---------------------------------------------------------------------------
// Binary conv + BN. One block per (n,h) output row; thread t = output channel.
// Zero-padded smem -> branch-free 9-tap XOR/popcount inner loop; padding and
// BN folded into a single FFMA epilogue with 3 precomputed bias variants.
// ---------------------------------------------------------------------------
__global__ void __launch_bounds__(256, 2)
conv_kernel(const float* __restrict__ gamma, const float* __restrict__ beta,
            const float* __restrict__ rmean, const float* __restrict__ rvar,
            float* __restrict__ out) {
    int b = blockIdx.x;            // n*56 + h
    int n = b / HH, h = b % HH;
    int t = threadIdx.x;           // co

    // Per-thread weight bits (coalesced loads, static-indexed -> registers)
    uint32_t wreg[9][NWORD];
    #pragma unroll
    for (int tap = 0; tap < 9; ++tap)
        #pragma unroll
        for (int wd = 0; wd < NWORD; ++wd)
            wreg[tap][wd] = g_wp[(tap * NWORD + wd) * COUT + t];

    // m[tap] = contribution of a zero-padded tap to the XNOR match count
    int m[9];
    #pragma unroll
    for (int tap = 0; tap < 9; ++tap) {
        int pw = 0;
        #pragma unroll
        for (int wd = 0; wd < NWORD; ++wd) pw += __popc(wreg[tap][wd]);
        m[tap] = 256 - pw;
    }

    // Stage 3 padded input rows into smem: layout [kh][col 0..57][word 0..7]
    __shared__ uint32_t xs[3][WPAD * NWORD];
    bool r0 = (h > 0), r2 = (h < HH - 1);
    bool rowok[3] = { r0, true, r2 };
    #pragma unroll
    for (int kh = 0; kh < 3; ++kh) {
        if (rowok[kh]) {
            // zero pad columns 0 and 57 (16 words)
            if (t < 2 * NWORD) {
                int c = (t < NWORD) ? 0 : (WPAD - 1);
                xs[kh][c * NWORD + (t & (NWORD - 1))] = 0u;
            }
            const uint32_t* src = &g_xp[((size_t)(n * HH + (h + kh - 1)) * WW) * NWORD];
            for (int i = t; i < WW * NWORD; i += 256)
                xs[kh][NWORD + i] = src[i];
        } else {
            for (int i = t; i < WPAD * NWORD; i += 256)
                xs[kh][i] = 0u;
        }
    }
    __syncthreads();

    // Fold BN + padding-correction + (2*match - 256*nv) into one FFMA.
    // accx = sum popc(x^w) over all 72 words (padded taps included).
    // out  = accx * (-2*iv) + c(Minv, nv)
    // c(Minv,nv) = (4608 - 2*Minv - 256*nv) * iv + bs
    float iv = gamma[t] * rsqrtf(rvar[t] + BN_EPS);
    float bs = fmaf(-rmean[t], iv, beta[t]);
    int rowcnt    = (int)r0 + 1 + (int)r2;
    int Minv_base = (r0 ? 0 : (m[0] + m[1] + m[2])) + (r2 ? 0 : (m[6] + m[7] + m[8]));
    int Mleft     = (r0 ? m[0] : 0) + m[3] + (r2 ? m[6] : 0);
    int Mright    = (r0 ? m[2] : 0) + m[5] + (r2 ? m[8] : 0);
    int nv_base   = 3 * rowcnt;
    float niv2    = -2.0f * iv;
    float c_mid   = fmaf((float)(4608 - 2 * Minv_base - 256 * nv_base), iv, bs);
    float c_left  = fmaf((float)(4608 - 2 * (Minv_base + Mleft)  - 256 * (nv_base - rowcnt)), iv, bs);
    float c_right = fmaf((float)(4608 - 2 * (Minv_base + Mright) - 256 * (nv_base - rowcnt)), iv, bs);

    float* op = out + (((size_t)n * COUT + t) * HH + h) * WW;

    #pragma unroll 2
    for (int w = 0; w < WW; ++w) {
        int accx = 0;
        #pragma unroll
        for (int kh = 0; kh < 3; ++kh) {
            #pragma unroll
            for (int kw = 0; kw < 3; ++kw) {
                const uint4* p = (const uint4*)&xs[kh][(w + kw) * NWORD];
                uint4 a = p[0];
                uint4 c = p[1];
                const uint32_t* wr = wreg[kh * 3 + kw];
                accx += __popc(a.x ^ wr[0]) + __popc(a.y ^ wr[1])
                      + __popc(a.z ^ wr[2]) + __popc(a.w ^ wr[3])
                      + __popc(c.x ^ wr[4]) + __popc(c.y ^ wr[5])
                      + __popc(c.z ^ wr[6]) + __popc(c.w ^ wr[7]);
            }
        }
        float cb = c_mid;
        if (w == 0)      cb = c_left;
        if (w == WW - 1) cb = c_right;
        op[w] = fmaf((float)accx, niv2, cb);
    }
}

// ---------------------------------------------------------------------------
extern "C" void kernel_launch(void* const* d_in, const int* in_sizes, int n_in,
                              void* d_out, int out_size) {
    const float* x     = (const float*)d_in[0];
    const float* wt    = (const float*)d_in[1];
    const float* gamma = (const float*)d_in[2];
    const float* beta  = (const float*)d_in[3];
    const float* rmean = (const float*)d_in[4];
    const float* rvar  = (const float*)d_in[5];
    float* out = (float*)d_out;

    pack_x_kernel<<<NB * HH, 512>>>(x);
    pack_w_kernel<<<(9 * NWORD * COUT + 255) / 256, 256>>>(wt);
    conv_kernel<<<NB * HH, 256>>>(gamma, beta, rmean, rvar, out);
}

// round 6
// speedup vs baseline: 1.0001x; 1.0001x over previous
#include <cuda_runtime.h>
#include <stdint.h>

// Problem constants
#define NB    32
#define CIN   256
#define HH    56
#define WW    56
#define COUT  256
#define NWORD 8          // 256 channels / 32 bits
#define WPAD  (WW + 2)   // zero-padded columns
#define BN_EPS 1e-5f

// Scratch (no allocations allowed): packed sign bits
// x packed: [n][h][w][word]   bit b of word wd = (x[n][32*wd+b][h][w] > 0)
__device__ uint32_t g_xp[(size_t)NB * HH * WW * NWORD];
// w packed: [tap][word][co]   (co contiguous -> coalesced register fill)
__device__ uint32_t g_wp[9 * NWORD * COUT];

// ---------------------------------------------------------------------------
// Pack activations: one block per (n,h); thread t -> (word wd, column w)
// ---------------------------------------------------------------------------
__global__ void pack_x_kernel(const float* __restrict__ x) {
    int b = blockIdx.x;            // n*56 + h
    int n = b / HH, h = b % HH;
    int t = threadIdx.x;
    if (t >= WW * NWORD) return;
    int wd = t / WW;
    int w  = t % WW;
    const float* xb = x + ((size_t)n * CIN + (size_t)wd * 32) * (HH * WW)
                        + (size_t)h * WW + w;
    uint32_t bits = 0;
    #pragma unroll
    for (int c = 0; c < 32; ++c) {
        float v = __ldg(xb + (size_t)c * (HH * WW));
        bits |= (v > 0.0f) ? (1u << c) : 0u;
    }
    g_xp[((size_t)b * WW + w) * NWORD + wd] = bits;
}

// ---------------------------------------------------------------------------
// Pack weights: gid = (tap*8 + wd)*256 + co
// ---------------------------------------------------------------------------
__global__ void pack_w_kernel(const float* __restrict__ wt) {
    int gid = blockIdx.x * blockDim.x + threadIdx.x;
    if (gid >= 9 * NWORD * COUT) return;
    int co  = gid & (COUT - 1);
    int tw  = gid >> 8;            // tap*8 + wd
    int tap = tw >> 3;
    int wd  = tw & 7;
    const float* wb = wt + ((size_t)co * CIN + (size_t)wd * 32) * 9 + tap;
    uint32_t bits = 0;
    #pragma unroll
    for (int c = 0; c < 32; ++c) {
        float v = __ldg(wb + c * 9);
        bits |= (v > 0.0f) ? (1u << c) : 0u;
    }
    g_wp[gid] = bits;
}

// ---------------------------------------------------------------------------
// Binary conv + BN. One block per (n,h) output row; thread t = output channel.
// Zero-padded smem -> branch-free 9-tap XOR/popcount inner loop; padding and
// BN folded into a single FFMA epilogue with 3 precomputed bias variants.
// ---------------------------------------------------------------------------
__global__ void __launch_bounds__(256, 2)
conv_kernel(const float* __restrict__ gamma, const float* __restrict__ beta,
            const float* __restrict__ rmean, const float* __restrict__ rvar,
            float* __restrict__ out) {
    int b = blockIdx.x;            // n*56 + h
    int n = b / HH, h = b % HH;
    int t = threadIdx.x;           // co

    // Per-thread weight bits (coalesced loads, static-indexed -> registers)
    uint32_t wreg[9][NWORD];
    #pragma unroll
    for (int tap = 0; tap < 9; ++tap)
        #pragma unroll
        for (int wd = 0; wd < NWORD; ++wd)
            wreg[tap][wd] = g_wp[(tap * NWORD + wd) * COUT + t];

    // m[tap] = contribution of a zero-padded tap to the XNOR match count
    int m[9];
    #pragma unroll
    for (int tap = 0; tap < 9; ++tap) {
        int pw = 0;
        #pragma unroll
        for (int wd = 0; wd < NWORD; ++wd) pw += __popc(wreg[tap][wd]);
        m[tap] = 256 - pw;
    }

    // Stage 3 padded input rows into smem: layout [kh][col 0..57][word 0..7]
    __shared__ uint32_t xs[3][WPAD * NWORD];
    bool r0 = (h > 0), r2 = (h < HH - 1);
    bool rowok[3] = { r0, true, r2 };
    #pragma unroll
    for (int kh = 0; kh < 3; ++kh) {
        if (rowok[kh]) {
            // zero pad columns 0 and 57 (16 words)
            if (t < 2 * NWORD) {
                int c = (t < NWORD) ? 0 : (WPAD - 1);
                xs[kh][c * NWORD + (t & (NWORD - 1))] = 0u;
            }
            const uint32_t* src = &g_xp[((size_t)(n * HH + (h + kh - 1)) * WW) * NWORD];
            for (int i = t; i < WW * NWORD; i += 256)
                xs[kh][NWORD + i] = src[i];
        } else {
            for (int i = t; i < WPAD * NWORD; i += 256)
                xs[kh][i] = 0u;
        }
    }
    __syncthreads();

    // Fold BN + padding-correction + (2*match - 256*nv) into one FFMA.
    // accx = sum popc(x^w) over all 72 words (padded taps included).
    // out  = accx * (-2*iv) + c(Minv, nv)
    // c(Minv,nv) = (4608 - 2*Minv - 256*nv) * iv + bs
    float iv = gamma[t] * rsqrtf(rvar[t] + BN_EPS);
    float bs = fmaf(-rmean[t], iv, beta[t]);
    int rowcnt    = (int)r0 + 1 + (int)r2;
    int Minv_base = (r0 ? 0 : (m[0] + m[1] + m[2])) + (r2 ? 0 : (m[6] + m[7] + m[8]));
    int Mleft     = (r0 ? m[0] : 0) + m[3] + (r2 ? m[6] : 0);
    int Mright    = (r0 ? m[2] : 0) + m[5] + (r2 ? m[8] : 0);
    int nv_base   = 3 * rowcnt;
    float niv2    = -2.0f * iv;
    float c_mid   = fmaf((float)(4608 - 2 * Minv_base - 256 * nv_base), iv, bs);
    float c_left  = fmaf((float)(4608 - 2 * (Minv_base + Mleft)  - 256 * (nv_base - rowcnt)), iv, bs);
    float c_right = fmaf((float)(4608 - 2 * (Minv_base + Mright) - 256 * (nv_base - rowcnt)), iv, bs);

    float* op = out + (((size_t)n * COUT + t) * HH + h) * WW;

    #pragma unroll 2
    for (int w = 0; w < WW; ++w) {
        int accx = 0;
        #pragma unroll
        for (int kh = 0; kh < 3; ++kh) {
            #pragma unroll
            for (int kw = 0; kw < 3; ++kw) {
                const uint4* p = (const uint4*)&xs[kh][(w + kw) * NWORD];
                uint4 a = p[0];
                uint4 c = p[1];
                const uint32_t* wr = wreg[kh * 3 + kw];
                accx += __popc(a.x ^ wr[0]) + __popc(a.y ^ wr[1])
                      + __popc(a.z ^ wr[2]) + __popc(a.w ^ wr[3])
                      + __popc(c.x ^ wr[4]) + __popc(c.y ^ wr[5])
                      + __popc(c.z ^ wr[6]) + __popc(c.w ^ wr[7]);
            }
        }
        float cb = c_mid;
        if (w == 0)      cb = c_left;
        if (w == WW - 1) cb = c_right;
        op[w] = fmaf((float)accx, niv2, cb);
    }
}

// ---------------------------------------------------------------------------
extern "C" void kernel_launch(void* const* d_in, const int* in_sizes, int n_in,
                              void* d_out, int out_size) {
    const float* x     = (const float*)d_in[0];
    const float* wt    = (const float*)d_in[1];
    const float* gamma = (const float*)d_in[2];
    const float* beta  = (const float*)d_in[3];
    const float* rmean = (const float*)d_in[4];
    const float* rvar  = (const float*)d_in[5];
    float* out = (float*)d_out;

    pack_x_kernel<<<NB * HH, 512>>>(x);
    pack_w_kernel<<<(9 * NWORD * COUT + 255) / 256, 256>>>(wt);
    conv_kernel<<<NB * HH, 256>>>(gamma, beta, rmean, rvar, out);
}